// round 15
// baseline (speedup 1.0000x reference)
#include <cuda_runtime.h>
#include <math.h>

constexpr int NB=128, NP=196, FEAT=2048, E=512, D=512, V=10000, L=52, T=51;
constexpr int G=2048, R=NB*T;

__device__ float d_fm[NB*FEAT];
__device__ float d_hA[NB*D];
__device__ float d_hB[NB*D];
__device__ float d_xproj[(size_t)R*G];
__device__ float d_Hbuf[(size_t)R*D];
__device__ float d_wT[(size_t)NB*8192];   // per-block transposed w_hh slice [k][16]
__device__ int d_sortind[NB], d_dlen[NB], d_start[NB], d_nt[T];
__device__ int d_S;
__device__ int d_tok[R], d_vrow[R];
__device__ float d_bias2[G];
__device__ volatile int d_flags2[NB];
__device__ volatile int d_gen2;

__device__ __forceinline__ void fma2(unsigned long long &d,
                                     unsigned long long a, unsigned long long b){
    asm("fma.rn.f32x2 %0, %1, %2, %0;" : "+l"(d) : "l"(a), "l"(b));
}
__device__ __forceinline__ unsigned long long dup2(float v){
    unsigned long long r; asm("mov.b64 %0, {%1, %1};" : "=l"(r) : "f"(v)); return r;
}
__device__ __forceinline__ float2 unpk(unsigned long long v){
    float2 f; asm("mov.b64 {%0, %1}, %2;" : "=f"(f.x), "=f"(f.y) : "l"(v)); return f;
}
__device__ __forceinline__ unsigned tf32_of(float f){
    unsigned u; asm("cvt.rna.tf32.f32 %0, %1;" : "=r"(u) : "f"(f)); return u;
}
__device__ __forceinline__ void mma_tf32(float* c, const unsigned* a, const unsigned* b){
    asm("mma.sync.aligned.m16n8k8.row.col.f32.tf32.tf32.f32 "
        "{%0,%1,%2,%3}, {%4,%5,%6,%7}, {%8,%9}, {%0,%1,%2,%3};"
        : "+f"(c[0]),"+f"(c[1]),"+f"(c[2]),"+f"(c[3])
        : "r"(a[0]),"r"(a[1]),"r"(a[2]),"r"(a[3]),"r"(b[0]),"r"(b[1]));
}

// ---------------------------------------------------------------------------
__global__ void prep_kernel(const int* __restrict__ clen,
                            const int* __restrict__ caps,
                            const float* __restrict__ b_ih,
                            const float* __restrict__ b_hh,
                            float* __restrict__ out, int write_tail)
{
    __shared__ int s_len[NB], s_dl[NB];
    int tid = threadIdx.x;
    if (tid == 0) d_gen2 = 0;
    d_flags2[tid] = 0;
    s_len[tid] = clen[tid];
    __syncthreads();
    int li = s_len[tid], rank = 0;
    for (int j = 0; j < NB; j++) {
        int lj = s_len[j];
        rank += (lj > li) || (lj == li && j < tid);
    }
    d_sortind[rank] = tid;
    __syncthreads();
    int src = d_sortind[tid];
    int dl  = s_len[src] - 1;
    d_dlen[tid] = dl;
    s_dl[tid] = dl;
    for (int r = tid; r < R; r += NB) { d_vrow[r] = 0; d_tok[r] = 0; }
    __syncthreads();
    if (tid < T) {
        int c = 0;
        for (int b = 0; b < NB; b++) c += (s_dl[b] > tid);
        d_nt[tid] = c;
    }
    int st = 0;
    for (int j = 0; j < tid; j++) st += s_dl[j];
    d_start[tid] = st;
    if (tid == NB - 1) d_S = st + dl;
    for (int t = 0; t < dl; t++) {
        d_vrow[st + t] = tid * T + t;
        d_tok[st + t]  = caps[src * L + t];
    }
    if (write_tail) {
        float* out_caps = out + (size_t)NB * T * V;
        float* out_dlen = out_caps + (size_t)NB * L;
        float* out_sort = out_dlen + NB;
        out_dlen[tid] = (float)dl;
        out_sort[tid] = (float)src;
        for (int j = 0; j < L; j++)
            out_caps[tid * L + j] = (float)caps[src * L + j];
    }
    for (int j = tid; j < G; j += NB) d_bias2[j] = b_ih[j] + b_hh[j];
}

// ---------------------------------------------------------------------------
// one-shot transpose: d_wT[blk][k][i] = w_hh[gc(i)][k], gc = (i>>2)*512+blk*4+(i&3)
// ---------------------------------------------------------------------------
__global__ void wtrans_kernel(const float* __restrict__ w_hh)
{
    int blk = blockIdx.x, tid = threadIdx.x;
    int d0 = blk * 4;
    float* wTb = d_wT + (size_t)blk * 8192;
    int i  = tid >> 4;            // col index 0..15
    int ks = (tid & 15) * 32;     // k segment
    int gc = (i >> 2) * 512 + d0 + (i & 3);
    const float* src = w_hh + (size_t)gc * 512 + ks;
    #pragma unroll 4
    for (int k = 0; k < 32; k++)
        wTb[(size_t)(ks + k) * 16 + i] = __ldg(&src[k]);
}

// ---------------------------------------------------------------------------
__global__ void mean_kernel(const float* __restrict__ feats)
{
    int b = blockIdx.x, src = d_sortind[b], tid = threadIdx.x;
    const float* base = feats + (size_t)src * NP * FEAT;
    float acc[FEAT / 256];
    #pragma unroll
    for (int j = 0; j < FEAT / 256; j++) acc[j] = 0.f;
    for (int p = 0; p < NP; p++) {
        const float* row = base + (size_t)p * FEAT;
        #pragma unroll
        for (int j = 0; j < FEAT / 256; j++) acc[j] += __ldg(&row[tid + j * 256]);
    }
    #pragma unroll
    for (int j = 0; j < FEAT / 256; j++)
        d_fm[b * FEAT + tid + j * 256] = acc[j] * (1.f / NP);
}

// ---------------------------------------------------------------------------
__global__ void h0_kernel(const float* __restrict__ att1_w,
                          const float* __restrict__ att1_b)
{
    __shared__ float s_fm[FEAT];
    int b = blockIdx.x, c0 = blockIdx.y * 128;
    for (int i = threadIdx.x; i < FEAT; i += 256) s_fm[i] = d_fm[b * FEAT + i];
    __syncthreads();
    int warp = threadIdx.x >> 5, lane = threadIdx.x & 31;
    for (int cc = warp; cc < 128; cc += 8) {
        int col = c0 + cc;
        const float4* wr = (const float4*)(att1_w + (size_t)col * FEAT);
        float s = 0.f;
        for (int k = lane; k < FEAT / 4; k += 32) {
            float4 w = __ldg(&wr[k]);
            float4 f = *(const float4*)&s_fm[k * 4];
            s += w.x * f.x + w.y * f.y + w.z * f.z + w.w * f.w;
        }
        #pragma unroll
        for (int o = 16; o; o >>= 1) s += __shfl_down_sync(~0u, s, o);
        if (!lane) d_hA[b * D + col] = s + __ldg(&att1_b[col]);
    }
}

// ---------------------------------------------------------------------------
// fp32 f32x2 GEMM (used for xproj). Proven rounds 5-12.
// ---------------------------------------------------------------------------
template<bool GA, bool SCAT>
__global__ __launch_bounds__(256, 2) void gemm128(
    const float* __restrict__ A, int lda, const int* __restrict__ aIdx,
    const float* __restrict__ Bm, const float* __restrict__ bias,
    float* __restrict__ Cout, int ldc, const int* __restrict__ outIdx,
    const int* __restrict__ MvP, int N, int K)
{
    __shared__ __align__(16) float As[2][16][132];
    __shared__ __align__(16) float Bs[2][16][132];
    __shared__ int s_src[128];

    int m0 = blockIdx.x * 128, n0 = blockIdx.y * 128;
    int Mv = MvP ? __ldg(MvP) : 0x7fffffff;
    if (m0 >= Mv) return;

    int tid = threadIdx.x;
    if (tid < 128) s_src[tid] = GA ? __ldg(&aIdx[m0 + tid]) : (m0 + tid);
    __syncthreads();

    int tx = tid & 15, ty = tid >> 4;
    int tx4 = tx * 4, ty4 = ty * 4;
    int j1 = tid + 256;
    int r0 = tid >> 2, q0 = tid & 3;
    int r1 = j1 >> 2,  q1 = j1 & 3;
    const float* Ar0 = A + (size_t)s_src[r0] * lda + q0 * 4;
    const float* Ar1 = A + (size_t)s_src[r1] * lda + q1 * 4;
    bool bok0 = (n0 + r0) < N, bok1 = (n0 + r1) < N;
    const float* Br0 = Bm + (size_t)(n0 + r0) * K + q0 * 4;
    const float* Br1 = Bm + (size_t)(n0 + r1) * K + q1 * 4;
    const float4 z4 = make_float4(0.f, 0.f, 0.f, 0.f);

    unsigned long long acc[4][8];
    #pragma unroll
    for (int p = 0; p < 4; p++)
        #pragma unroll
        for (int j = 0; j < 8; j++) acc[p][j] = 0ull;

    float4 ra0 = __ldg((const float4*)Ar0);
    float4 ra1 = __ldg((const float4*)Ar1);
    float4 rb0 = bok0 ? __ldg((const float4*)Br0) : z4;
    float4 rb1 = bok1 ? __ldg((const float4*)Br1) : z4;
    As[0][q0*4+0][r0]=ra0.x; As[0][q0*4+1][r0]=ra0.y; As[0][q0*4+2][r0]=ra0.z; As[0][q0*4+3][r0]=ra0.w;
    As[0][q1*4+0][r1]=ra1.x; As[0][q1*4+1][r1]=ra1.y; As[0][q1*4+2][r1]=ra1.z; As[0][q1*4+3][r1]=ra1.w;
    Bs[0][q0*4+0][r0]=rb0.x; Bs[0][q0*4+1][r0]=rb0.y; Bs[0][q0*4+2][r0]=rb0.z; Bs[0][q0*4+3][r0]=rb0.w;
    Bs[0][q1*4+0][r1]=rb1.x; Bs[0][q1*4+1][r1]=rb1.y; Bs[0][q1*4+2][r1]=rb1.z; Bs[0][q1*4+3][r1]=rb1.w;
    __syncthreads();

    const int KT = K / 16;
    for (int kt = 0; kt < KT; kt++) {
        int cur = kt & 1;
        if (kt + 1 < KT) {
            int ko = (kt + 1) * 16;
            ra0 = __ldg((const float4*)(Ar0 + ko));
            ra1 = __ldg((const float4*)(Ar1 + ko));
            rb0 = bok0 ? __ldg((const float4*)(Br0 + ko)) : z4;
            rb1 = bok1 ? __ldg((const float4*)(Br1 + ko)) : z4;
        }
        #pragma unroll
        for (int k = 0; k < 16; k++) {
            ulonglong2 a01 = *(const ulonglong2*)&As[cur][k][ty4];
            ulonglong2 a23 = *(const ulonglong2*)&As[cur][k][ty4 + 64];
            float4 b0 = *(const float4*)&Bs[cur][k][tx4];
            float4 b1 = *(const float4*)&Bs[cur][k][tx4 + 64];
            unsigned long long pa[4] = {a01.x, a01.y, a23.x, a23.y};
            unsigned long long pb[8] = {dup2(b0.x), dup2(b0.y), dup2(b0.z), dup2(b0.w),
                                        dup2(b1.x), dup2(b1.y), dup2(b1.z), dup2(b1.w)};
            #pragma unroll
            for (int p = 0; p < 4; p++)
                #pragma unroll
                for (int j = 0; j < 8; j++)
                    fma2(acc[p][j], pa[p], pb[j]);
        }
        if (kt + 1 < KT) {
            int nb = 1 - cur;
            As[nb][q0*4+0][r0]=ra0.x; As[nb][q0*4+1][r0]=ra0.y; As[nb][q0*4+2][r0]=ra0.z; As[nb][q0*4+3][r0]=ra0.w;
            As[nb][q1*4+0][r1]=ra1.x; As[nb][q1*4+1][r1]=ra1.y; As[nb][q1*4+2][r1]=ra1.z; As[nb][q1*4+3][r1]=ra1.w;
            Bs[nb][q0*4+0][r0]=rb0.x; Bs[nb][q0*4+1][r0]=rb0.y; Bs[nb][q0*4+2][r0]=rb0.z; Bs[nb][q0*4+3][r0]=rb0.w;
            Bs[nb][q1*4+0][r1]=rb1.x; Bs[nb][q1*4+1][r1]=rb1.y; Bs[nb][q1*4+2][r1]=rb1.z; Bs[nb][q1*4+3][r1]=rb1.w;
        }
        __syncthreads();
    }

    bool cok0 = (n0 + tx4) < N, cok1 = (n0 + tx4 + 64) < N;
    float4 bi0 = z4, bi1 = z4;
    if (bias) {
        if (cok0) bi0 = __ldg((const float4*)(bias + n0 + tx4));
        if (cok1) bi1 = __ldg((const float4*)(bias + n0 + tx4 + 64));
    }
    #pragma unroll
    for (int p = 0; p < 4; p++) {
        int rbase = m0 + ((p < 2) ? (ty4 + 2 * p) : (64 + ty4 + 2 * (p - 2)));
        float2 u[8];
        #pragma unroll
        for (int j = 0; j < 8; j++) u[j] = unpk(acc[p][j]);
        float4 lo0 = make_float4(u[0].x+bi0.x, u[1].x+bi0.y, u[2].x+bi0.z, u[3].x+bi0.w);
        float4 lo1 = make_float4(u[4].x+bi1.x, u[5].x+bi1.y, u[6].x+bi1.z, u[7].x+bi1.w);
        float4 hi0 = make_float4(u[0].y+bi0.x, u[1].y+bi0.y, u[2].y+bi0.z, u[3].y+bi0.w);
        float4 hi1 = make_float4(u[4].y+bi1.x, u[5].y+bi1.y, u[6].y+bi1.z, u[7].y+bi1.w);
        if (!SCAT || rbase < Mv) {
            size_t orow = SCAT ? (size_t)__ldg(&outIdx[rbase]) : (size_t)rbase;
            if (cok0) *(float4*)(Cout + orow * ldc + n0 + tx4)      = lo0;
            if (cok1) *(float4*)(Cout + orow * ldc + n0 + tx4 + 64) = lo1;
        }
        int rh = rbase + 1;
        if (!SCAT || rh < Mv) {
            size_t orow = SCAT ? (size_t)__ldg(&outIdx[rh]) : (size_t)rh;
            if (cok0) *(float4*)(Cout + orow * ldc + n0 + tx4)      = hi0;
            if (cok1) *(float4*)(Cout + orow * ldc + n0 + tx4 + 64) = hi1;
        }
    }
}

// ---------------------------------------------------------------------------
// tf32 word projection v3 — byte-identical to the round-12 PASSING version.
// ---------------------------------------------------------------------------
__global__ __launch_bounds__(256) void word_mma(
    const float* __restrict__ A, const float* __restrict__ Bm,
    const float* __restrict__ bias, float* __restrict__ Cout,
    const int* __restrict__ outIdx, const int* __restrict__ MvP)
{
    constexpr int ST = 20;
    __shared__ __align__(16) unsigned As[2][128 * ST];
    __shared__ __align__(16) unsigned Bs[2][128 * ST];

    int m0 = blockIdx.x * 128, n0 = blockIdx.y * 128;
    int Mv = __ldg(MvP);
    if (m0 >= Mv) return;

    int tid = threadIdx.x, lane = tid & 31, w = tid >> 5;
    int wm = w & 3, wn = w >> 2;
    int lrow = tid >> 2, q = tid & 3;
    const float4 z4 = make_float4(0.f, 0.f, 0.f, 0.f);

    const float4* Ag0 = (const float4*)(A + (size_t)(m0 + lrow)      * D) + q;
    const float4* Ag1 = (const float4*)(A + (size_t)(m0 + lrow + 64) * D) + q;
    int br0 = n0 + lrow, br1 = n0 + lrow + 64;
    bool bok0 = br0 < V, bok1 = br1 < V;
    const float4* Bg0 = (const float4*)(Bm + (size_t)(bok0 ? br0 : 0) * D) + q;
    const float4* Bg1 = (const float4*)(Bm + (size_t)(bok1 ? br1 : 0) * D) + q;

    int s0 = lrow * ST + q * 4;
    int s1 = (lrow + 64) * ST + q * 4;

    float acc[2][8][4];
    #pragma unroll
    for (int i = 0; i < 2; i++)
        #pragma unroll
        for (int j = 0; j < 8; j++)
            #pragma unroll
            for (int r = 0; r < 4; r++) acc[i][j][r] = 0.f;

    float4 pa0 = __ldg(Ag0), pa1 = __ldg(Ag1);
    float4 pb0 = bok0 ? __ldg(Bg0) : z4;
    float4 pb1 = bok1 ? __ldg(Bg1) : z4;
    {
        uint4 u;
        u.x=tf32_of(pa0.x); u.y=tf32_of(pa0.y); u.z=tf32_of(pa0.z); u.w=tf32_of(pa0.w);
        *(uint4*)&As[0][s0] = u;
        u.x=tf32_of(pa1.x); u.y=tf32_of(pa1.y); u.z=tf32_of(pa1.z); u.w=tf32_of(pa1.w);
        *(uint4*)&As[0][s1] = u;
        u.x=tf32_of(pb0.x); u.y=tf32_of(pb0.y); u.z=tf32_of(pb0.z); u.w=tf32_of(pb0.w);
        *(uint4*)&Bs[0][s0] = u;
        u.x=tf32_of(pb1.x); u.y=tf32_of(pb1.y); u.z=tf32_of(pb1.z); u.w=tf32_of(pb1.w);
        *(uint4*)&Bs[0][s1] = u;
    }
    __syncthreads();

    int g = lane >> 2, t4 = lane & 3;
    const int KT = D / 16;
    for (int kt = 0; kt < KT; kt++) {
        int cur = kt & 1;
        if (kt + 1 < KT) {
            int ko = (kt + 1) * 4;
            pa0 = __ldg(Ag0 + ko); pa1 = __ldg(Ag1 + ko);
            pb0 = bok0 ? __ldg(Bg0 + ko) : z4;
            pb1 = bok1 ? __ldg(Bg1 + ko) : z4;
        }
        #pragma unroll
        for (int ks = 0; ks < 2; ks++) {
            int kb = ks * 8;
            unsigned af[2][4], bf[8][2];
            #pragma unroll
            for (int i = 0; i < 2; i++) {
                int base = (wm * 32 + i * 16 + g) * ST + kb + t4;
                af[i][0] = As[cur][base];
                af[i][1] = As[cur][base + 8 * ST];
                af[i][2] = As[cur][base + 4];
                af[i][3] = As[cur][base + 8 * ST + 4];
            }
            #pragma unroll
            for (int j = 0; j < 8; j++) {
                int base = (wn * 64 + j * 8 + g) * ST + kb + t4;
                bf[j][0] = Bs[cur][base];
                bf[j][1] = Bs[cur][base + 4];
            }
            #pragma unroll
            for (int i = 0; i < 2; i++)
                #pragma unroll
                for (int j = 0; j < 8; j++)
                    mma_tf32(acc[i][j], af[i], bf[j]);
        }
        if (kt + 1 < KT) {
            int nb = 1 - cur;
            uint4 u;
            u.x=tf32_of(pa0.x); u.y=tf32_of(pa0.y); u.z=tf32_of(pa0.z); u.w=tf32_of(pa0.w);
            *(uint4*)&As[nb][s0] = u;
            u.x=tf32_of(pa1.x); u.y=tf32_of(pa1.y); u.z=tf32_of(pa1.z); u.w=tf32_of(pa1.w);
            *(uint4*)&As[nb][s1] = u;
            u.x=tf32_of(pb0.x); u.y=tf32_of(pb0.y); u.z=tf32_of(pb0.z); u.w=tf32_of(pb0.w);
            *(uint4*)&Bs[nb][s0] = u;
            u.x=tf32_of(pb1.x); u.y=tf32_of(pb1.y); u.z=tf32_of(pb1.z); u.w=tf32_of(pb1.w);
            *(uint4*)&Bs[nb][s1] = u;
        }
        __syncthreads();
    }

    int r0 = lane >> 2, tg = lane & 3;
    #pragma unroll
    for (int i = 0; i < 2; i++) {
        #pragma unroll
        for (int h = 0; h < 2; h++) {
            int gr = m0 + wm * 32 + i * 16 + r0 + h * 8;
            if (gr < Mv) {
                size_t orow = (size_t)__ldg(&outIdx[gr]);
                float* outr = Cout + orow * V;
                #pragma unroll
                for (int j = 0; j < 8; j++) {
                    int gc = n0 + wn * 64 + j * 8 + tg * 2;
                    if (gc < V) {
                        float b0 = __ldg(&bias[gc]), b1 = __ldg(&bias[gc + 1]);
                        float2 v;
                        v.x = acc[i][j][h * 2 + 0] + b0;
                        v.y = acc[i][j][h * 2 + 1] + b1;
                        *(float2*)(outr + gc) = v;
                    }
                }
            }
        }
    }
}

// ---------------------------------------------------------------------------
__global__ void zerofill(float* __restrict__ out)
{
    int r = blockIdx.x, b = r / T, t = r - b * T;
    if (t < d_dlen[b]) return;
    float4* p = (float4*)(out + (size_t)r * V);
    float4 z = make_float4(0.f, 0.f, 0.f, 0.f);
    for (int i = threadIdx.x; i < V / 4; i += blockDim.x) p[i] = z;
}

// ---------------------------------------------------------------------------
// persistent LSTM v4 (static smem only, 36.6KB):
//  - w read from d_wT via __ldg (L1-resident 32KB/block), smem freed
//  - k=32 chunks, double-buffered hsb[2][32][132]: 1 sync/chunk (18/step)
//  - full-chunk register prefetch (4 x float4)
//  - single-hop all-poll grid barrier
// Same k-accumulation order per (row,col) => bit-identical results.
// ---------------------------------------------------------------------------
__global__ __launch_bounds__(256) void lstm_persist()
{
    __shared__ __align__(16) float hsb[2][32][132];
    __shared__ float c_s[512];
    __shared__ int s_start[NB];
    __shared__ int s_nt[T];

    int tid = threadIdx.x, blk = blockIdx.x, d0 = blk * 4;
    const float4* wT4 = (const float4*)(d_wT + (size_t)blk * 8192);

    if (tid < NB) s_start[tid] = d_start[tid];
    if (tid < T)  s_nt[tid] = d_nt[tid];
    for (int e = tid; e < 512; e += 256) c_s[e] = 0.f;
    __syncthreads();

    int rp = tid >> 2, c4 = tid & 3;       // compute: rows 2rp,2rp+1 x cols 4c4..+3
    int lrow = tid & 127, seg = tid >> 7;  // load: row lrow, k-quarter seg*16

    for (int t = 0; t < T; t++) {
        int nt = s_nt[t], nt8 = (nt + 7) & ~7;
        bool cok = (2 * rp) < nt8;
        bool lok = lrow < nt8;
        const float* hc = (t & 1) ? d_hB : d_hA;
        float*       hw = (t & 1) ? d_hA : d_hB;
        const float* hrow = hc + (size_t)lrow * 512 + seg * 16;

        unsigned long long acc[4] = {0ull, 0ull, 0ull, 0ull};
        float4 pv[4];

        if (lok) {                          // prologue: chunk 0 (k 0..31)
            #pragma unroll
            for (int f = 0; f < 4; f++) pv[f] = __ldcg((const float4*)(hrow + f * 4));
            #pragma unroll
            for (int f = 0; f < 4; f++) {
                int kk = seg * 16 + f * 4;
                hsb[0][kk+0][lrow]=pv[f].x; hsb[0][kk+1][lrow]=pv[f].y;
                hsb[0][kk+2][lrow]=pv[f].z; hsb[0][kk+3][lrow]=pv[f].w;
            }
        }
        __syncthreads();

        for (int c = 0; c < 16; c++) {
            int cur = c & 1;
            if (c + 1 < 16 && lok) {
                const float* hn = hrow + (c + 1) * 32;
                #pragma unroll
                for (int f = 0; f < 4; f++) pv[f] = __ldcg((const float4*)(hn + f * 4));
            }
            if (cok) {
                #pragma unroll
                for (int k = 0; k < 32; k++) {
                    unsigned long long hp = *(const unsigned long long*)&hsb[cur][k][rp * 2];
                    float4 wv = __ldg(&wT4[(c * 32 + k) * 4 + c4]);
                    fma2(acc[0], hp, dup2(wv.x));
                    fma2(acc[1], hp, dup2(wv.y));
                    fma2(acc[2], hp, dup2(wv.z));
                    fma2(acc[3], hp, dup2(wv.w));
                }
            }
            if (c + 1 < 16 && lok) {
                int nb = 1 - cur;
                #pragma unroll
                for (int f = 0; f < 4; f++) {
                    int kk = seg * 16 + f * 4;
                    hsb[nb][kk+0][lrow]=pv[f].x; hsb[nb][kk+1][lrow]=pv[f].y;
                    hsb[nb][kk+2][lrow]=pv[f].z; hsb[nb][kk+3][lrow]=pv[f].w;
                }
            }
            __syncthreads();
        }

        // gates stash into buffer 0 (last chunk c=15 computed on buffer 1)
        #pragma unroll
        for (int j = 0; j < 4; j++) {
            float2 f = unpk(acc[j]);
            hsb[0][c4 * 4 + j][rp * 2 + 0] = f.x;
            hsb[0][c4 * 4 + j][rp * 2 + 1] = f.y;
        }
        __syncthreads();
        for (int e = tid; e < 512; e += 256) {
            int b = e >> 2, dd = e & 3;
            if (b < nt) {
                size_t cidx = (size_t)(s_start[b] + t);
                const float* xp = d_xproj + cidx * G + d0 + dd;
                float g0 = hsb[0][dd][b]      + __ldg(xp);
                float g1 = hsb[0][4 + dd][b]  + __ldg(xp + 512);
                float g2 = hsb[0][8 + dd][b]  + __ldg(xp + 1024);
                float g3 = hsb[0][12 + dd][b] + __ldg(xp + 1536);
                float gi = 1.f / (1.f + __expf(-g0));
                float gf = 1.f / (1.f + __expf(-g1));
                float gg = tanhf(g2);
                float go = 1.f / (1.f + __expf(-g3));
                float c  = c_s[e];
                float cn = gf * c + gi * gg;
                float hn = go * tanhf(cn);
                c_s[e] = cn;
                __stcg(hw + (size_t)b * 512 + d0 + dd, hn);
                d_Hbuf[cidx * 512 + d0 + dd] = hn;
            }
        }
        // single-hop grid barrier: everyone polls all 128 flags
        if (t < T - 1) {
            int tg2 = t + 1;
            __syncthreads();
            if (tid == 0) { __threadfence(); d_flags2[blk] = tg2; }
            if (tid < NB) {
                while (d_flags2[tid] < tg2) __nanosleep(32);
                __threadfence();
            }
            __syncthreads();
        }
    }
}

// ---------------------------------------------------------------------------
extern "C" void kernel_launch(void* const* d_in, const int* in_sizes, int n_in,
                              void* d_out, int out_size)
{
    const float* feats  = (const float*)d_in[0];
    const int*   caps   = (const int*)  d_in[1];
    const int*   clen   = (const int*)  d_in[2];
    const float* emb    = (const float*)d_in[3];
    const float* att1_w = (const float*)d_in[4];
    const float* att1_b = (const float*)d_in[5];
    const float* w_ih   = (const float*)d_in[6];
    const float* w_hh   = (const float*)d_in[7];
    const float* b_ih   = (const float*)d_in[8];
    const float* b_hh   = (const float*)d_in[9];
    const float* word_w = (const float*)d_in[10];
    const float* word_b = (const float*)d_in[11];
    float* out = (float*)d_out;

    float *xproj, *Hbuf, *bias2;
    int *tok, *vrow, *Sp;
    cudaGetSymbolAddress((void**)&xproj, d_xproj);
    cudaGetSymbolAddress((void**)&Hbuf,  d_Hbuf);
    cudaGetSymbolAddress((void**)&bias2, d_bias2);
    cudaGetSymbolAddress((void**)&tok,   d_tok);
    cudaGetSymbolAddress((void**)&vrow,  d_vrow);
    cudaGetSymbolAddress((void**)&Sp,    d_S);

    const long long PRED = (long long)NB * T * V;
    int write_tail = ((long long)out_size >= PRED + NB * L + 2 * NB) ? 1 : 0;

    prep_kernel<<<1, NB>>>(clen, caps, b_ih, b_hh, out, write_tail);
    wtrans_kernel<<<NB, 256>>>(w_hh);
    mean_kernel<<<NB, 256>>>(feats);
    h0_kernel<<<dim3(NB, 4), 256>>>(att1_w, att1_b);

    gemm128<true, false><<<dim3(R / 128, G / 128), 256>>>(
        emb, E, tok, w_ih, bias2, xproj, G, nullptr, Sp, G, E);

    zerofill<<<R, 256>>>(out);

    lstm_persist<<<NB, 256>>>();

    word_mma<<<dim3((R + 127) / 128, (V + 127) / 128), 256>>>(
        Hbuf, word_w, word_b, out, vrow, Sp);
}

// round 17
// speedup vs baseline: 1.6328x; 1.6328x over previous
#include <cuda_runtime.h>
#include <math.h>

constexpr int NB=128, NP=196, FEAT=2048, E=512, D=512, V=10000, L=52, T=51;
constexpr int G=2048, R=NB*T;

__device__ float d_fm[NB*FEAT];
__device__ float d_hA[NB*D];
__device__ float d_hB[NB*D];
__device__ float d_xproj[(size_t)R*G];
__device__ float d_Hbuf[(size_t)R*D];
__device__ int d_sortind[NB], d_dlen[NB], d_start[NB], d_nt[T];
__device__ int d_S;
__device__ int d_tok[R], d_vrow[R];
__device__ float d_bias2[G];
__device__ volatile int d_flags2[NB];   // per-block arrival flags (reset by prep)
__device__ volatile int d_gen2;         // release word (reset by prep)

__device__ __forceinline__ void fma2(unsigned long long &d,
                                     unsigned long long a, unsigned long long b){
    asm("fma.rn.f32x2 %0, %1, %2, %0;" : "+l"(d) : "l"(a), "l"(b));
}
__device__ __forceinline__ unsigned long long dup2(float v){
    unsigned long long r; asm("mov.b64 %0, {%1, %1};" : "=l"(r) : "f"(v)); return r;
}
__device__ __forceinline__ float2 unpk(unsigned long long v){
    float2 f; asm("mov.b64 {%0, %1}, %2;" : "=f"(f.x), "=f"(f.y) : "l"(v)); return f;
}
__device__ __forceinline__ unsigned tf32_of(float f){
    unsigned u; asm("cvt.rna.tf32.f32 %0, %1;" : "=r"(u) : "f"(f)); return u;
}
__device__ __forceinline__ void mma_tf32(float* c, const unsigned* a, const unsigned* b){
    asm("mma.sync.aligned.m16n8k8.row.col.f32.tf32.tf32.f32 "
        "{%0,%1,%2,%3}, {%4,%5,%6,%7}, {%8,%9}, {%0,%1,%2,%3};"
        : "+f"(c[0]),"+f"(c[1]),"+f"(c[2]),"+f"(c[3])
        : "r"(a[0]),"r"(a[1]),"r"(a[2]),"r"(a[3]),"r"(b[0]),"r"(b[1]));
}

// ---------------------------------------------------------------------------
__global__ void prep_kernel(const int* __restrict__ clen,
                            const int* __restrict__ caps,
                            const float* __restrict__ b_ih,
                            const float* __restrict__ b_hh,
                            float* __restrict__ out, int write_tail)
{
    __shared__ int s_len[NB], s_dl[NB];
    int tid = threadIdx.x;
    if (tid == 0) d_gen2 = 0;
    d_flags2[tid] = 0;
    s_len[tid] = clen[tid];
    __syncthreads();
    int li = s_len[tid], rank = 0;
    for (int j = 0; j < NB; j++) {
        int lj = s_len[j];
        rank += (lj > li) || (lj == li && j < tid);
    }
    d_sortind[rank] = tid;
    __syncthreads();
    int src = d_sortind[tid];
    int dl  = s_len[src] - 1;
    d_dlen[tid] = dl;
    s_dl[tid] = dl;
    for (int r = tid; r < R; r += NB) { d_vrow[r] = 0; d_tok[r] = 0; }
    __syncthreads();
    if (tid < T) {
        int c = 0;
        for (int b = 0; b < NB; b++) c += (s_dl[b] > tid);
        d_nt[tid] = c;
    }
    int st = 0;
    for (int j = 0; j < tid; j++) st += s_dl[j];
    d_start[tid] = st;
    if (tid == NB - 1) d_S = st + dl;
    for (int t = 0; t < dl; t++) {
        d_vrow[st + t] = tid * T + t;
        d_tok[st + t]  = caps[src * L + t];
    }
    if (write_tail) {
        float* out_caps = out + (size_t)NB * T * V;
        float* out_dlen = out_caps + (size_t)NB * L;
        float* out_sort = out_dlen + NB;
        out_dlen[tid] = (float)dl;
        out_sort[tid] = (float)src;
        for (int j = 0; j < L; j++)
            out_caps[tid * L + j] = (float)caps[src * L + j];
    }
    for (int j = tid; j < G; j += NB) d_bias2[j] = b_ih[j] + b_hh[j];
}

// ---------------------------------------------------------------------------
__global__ void mean_kernel(const float* __restrict__ feats)
{
    int b = blockIdx.x, src = d_sortind[b], tid = threadIdx.x;
    const float* base = feats + (size_t)src * NP * FEAT;
    float acc[FEAT / 256];
    #pragma unroll
    for (int j = 0; j < FEAT / 256; j++) acc[j] = 0.f;
    for (int p = 0; p < NP; p++) {
        const float* row = base + (size_t)p * FEAT;
        #pragma unroll
        for (int j = 0; j < FEAT / 256; j++) acc[j] += __ldg(&row[tid + j * 256]);
    }
    #pragma unroll
    for (int j = 0; j < FEAT / 256; j++)
        d_fm[b * FEAT + tid + j * 256] = acc[j] * (1.f / NP);
}

// ---------------------------------------------------------------------------
__global__ void h0_kernel(const float* __restrict__ att1_w,
                          const float* __restrict__ att1_b)
{
    __shared__ float s_fm[FEAT];
    int b = blockIdx.x, c0 = blockIdx.y * 128;
    for (int i = threadIdx.x; i < FEAT; i += 256) s_fm[i] = d_fm[b * FEAT + i];
    __syncthreads();
    int warp = threadIdx.x >> 5, lane = threadIdx.x & 31;
    for (int cc = warp; cc < 128; cc += 8) {
        int col = c0 + cc;
        const float4* wr = (const float4*)(att1_w + (size_t)col * FEAT);
        float s = 0.f;
        for (int k = lane; k < FEAT / 4; k += 32) {
            float4 w = __ldg(&wr[k]);
            float4 f = *(const float4*)&s_fm[k * 4];
            s += w.x * f.x + w.y * f.y + w.z * f.z + w.w * f.w;
        }
        #pragma unroll
        for (int o = 16; o; o >>= 1) s += __shfl_down_sync(~0u, s, o);
        if (!lane) d_hA[b * D + col] = s + __ldg(&att1_b[col]);
    }
}

// ---------------------------------------------------------------------------
// fp32 f32x2 GEMM (used for xproj). Proven rounds 5-12.
// ---------------------------------------------------------------------------
template<bool GA, bool SCAT>
__global__ __launch_bounds__(256, 2) void gemm128(
    const float* __restrict__ A, int lda, const int* __restrict__ aIdx,
    const float* __restrict__ Bm, const float* __restrict__ bias,
    float* __restrict__ Cout, int ldc, const int* __restrict__ outIdx,
    const int* __restrict__ MvP, int N, int K)
{
    __shared__ __align__(16) float As[2][16][132];
    __shared__ __align__(16) float Bs[2][16][132];
    __shared__ int s_src[128];

    int m0 = blockIdx.x * 128, n0 = blockIdx.y * 128;
    int Mv = MvP ? __ldg(MvP) : 0x7fffffff;
    if (m0 >= Mv) return;

    int tid = threadIdx.x;
    if (tid < 128) s_src[tid] = GA ? __ldg(&aIdx[m0 + tid]) : (m0 + tid);
    __syncthreads();

    int tx = tid & 15, ty = tid >> 4;
    int tx4 = tx * 4, ty4 = ty * 4;
    int j1 = tid + 256;
    int r0 = tid >> 2, q0 = tid & 3;
    int r1 = j1 >> 2,  q1 = j1 & 3;
    const float* Ar0 = A + (size_t)s_src[r0] * lda + q0 * 4;
    const float* Ar1 = A + (size_t)s_src[r1] * lda + q1 * 4;
    bool bok0 = (n0 + r0) < N, bok1 = (n0 + r1) < N;
    const float* Br0 = Bm + (size_t)(n0 + r0) * K + q0 * 4;
    const float* Br1 = Bm + (size_t)(n0 + r1) * K + q1 * 4;
    const float4 z4 = make_float4(0.f, 0.f, 0.f, 0.f);

    unsigned long long acc[4][8];
    #pragma unroll
    for (int p = 0; p < 4; p++)
        #pragma unroll
        for (int j = 0; j < 8; j++) acc[p][j] = 0ull;

    float4 ra0 = __ldg((const float4*)Ar0);
    float4 ra1 = __ldg((const float4*)Ar1);
    float4 rb0 = bok0 ? __ldg((const float4*)Br0) : z4;
    float4 rb1 = bok1 ? __ldg((const float4*)Br1) : z4;
    As[0][q0*4+0][r0]=ra0.x; As[0][q0*4+1][r0]=ra0.y; As[0][q0*4+2][r0]=ra0.z; As[0][q0*4+3][r0]=ra0.w;
    As[0][q1*4+0][r1]=ra1.x; As[0][q1*4+1][r1]=ra1.y; As[0][q1*4+2][r1]=ra1.z; As[0][q1*4+3][r1]=ra1.w;
    Bs[0][q0*4+0][r0]=rb0.x; Bs[0][q0*4+1][r0]=rb0.y; Bs[0][q0*4+2][r0]=rb0.z; Bs[0][q0*4+3][r0]=rb0.w;
    Bs[0][q1*4+0][r1]=rb1.x; Bs[0][q1*4+1][r1]=rb1.y; Bs[0][q1*4+2][r1]=rb1.z; Bs[0][q1*4+3][r1]=rb1.w;
    __syncthreads();

    const int KT = K / 16;
    for (int kt = 0; kt < KT; kt++) {
        int cur = kt & 1;
        if (kt + 1 < KT) {
            int ko = (kt + 1) * 16;
            ra0 = __ldg((const float4*)(Ar0 + ko));
            ra1 = __ldg((const float4*)(Ar1 + ko));
            rb0 = bok0 ? __ldg((const float4*)(Br0 + ko)) : z4;
            rb1 = bok1 ? __ldg((const float4*)(Br1 + ko)) : z4;
        }
        #pragma unroll
        for (int k = 0; k < 16; k++) {
            ulonglong2 a01 = *(const ulonglong2*)&As[cur][k][ty4];
            ulonglong2 a23 = *(const ulonglong2*)&As[cur][k][ty4 + 64];
            float4 b0 = *(const float4*)&Bs[cur][k][tx4];
            float4 b1 = *(const float4*)&Bs[cur][k][tx4 + 64];
            unsigned long long pa[4] = {a01.x, a01.y, a23.x, a23.y};
            unsigned long long pb[8] = {dup2(b0.x), dup2(b0.y), dup2(b0.z), dup2(b0.w),
                                        dup2(b1.x), dup2(b1.y), dup2(b1.z), dup2(b1.w)};
            #pragma unroll
            for (int p = 0; p < 4; p++)
                #pragma unroll
                for (int j = 0; j < 8; j++)
                    fma2(acc[p][j], pa[p], pb[j]);
        }
        if (kt + 1 < KT) {
            int nb = 1 - cur;
            As[nb][q0*4+0][r0]=ra0.x; As[nb][q0*4+1][r0]=ra0.y; As[nb][q0*4+2][r0]=ra0.z; As[nb][q0*4+3][r0]=ra0.w;
            As[nb][q1*4+0][r1]=ra1.x; As[nb][q1*4+1][r1]=ra1.y; As[nb][q1*4+2][r1]=ra1.z; As[nb][q1*4+3][r1]=ra1.w;
            Bs[nb][q0*4+0][r0]=rb0.x; Bs[nb][q0*4+1][r0]=rb0.y; Bs[nb][q0*4+2][r0]=rb0.z; Bs[nb][q0*4+3][r0]=rb0.w;
            Bs[nb][q1*4+0][r1]=rb1.x; Bs[nb][q1*4+1][r1]=rb1.y; Bs[nb][q1*4+2][r1]=rb1.z; Bs[nb][q1*4+3][r1]=rb1.w;
        }
        __syncthreads();
    }

    bool cok0 = (n0 + tx4) < N, cok1 = (n0 + tx4 + 64) < N;
    float4 bi0 = z4, bi1 = z4;
    if (bias) {
        if (cok0) bi0 = __ldg((const float4*)(bias + n0 + tx4));
        if (cok1) bi1 = __ldg((const float4*)(bias + n0 + tx4 + 64));
    }
    #pragma unroll
    for (int p = 0; p < 4; p++) {
        int rbase = m0 + ((p < 2) ? (ty4 + 2 * p) : (64 + ty4 + 2 * (p - 2)));
        float2 u[8];
        #pragma unroll
        for (int j = 0; j < 8; j++) u[j] = unpk(acc[p][j]);
        float4 lo0 = make_float4(u[0].x+bi0.x, u[1].x+bi0.y, u[2].x+bi0.z, u[3].x+bi0.w);
        float4 lo1 = make_float4(u[4].x+bi1.x, u[5].x+bi1.y, u[6].x+bi1.z, u[7].x+bi1.w);
        float4 hi0 = make_float4(u[0].y+bi0.x, u[1].y+bi0.y, u[2].y+bi0.z, u[3].y+bi0.w);
        float4 hi1 = make_float4(u[4].y+bi1.x, u[5].y+bi1.y, u[6].y+bi1.z, u[7].y+bi1.w);
        if (!SCAT || rbase < Mv) {
            size_t orow = SCAT ? (size_t)__ldg(&outIdx[rbase]) : (size_t)rbase;
            if (cok0) *(float4*)(Cout + orow * ldc + n0 + tx4)      = lo0;
            if (cok1) *(float4*)(Cout + orow * ldc + n0 + tx4 + 64) = lo1;
        }
        int rh = rbase + 1;
        if (!SCAT || rh < Mv) {
            size_t orow = SCAT ? (size_t)__ldg(&outIdx[rh]) : (size_t)rh;
            if (cok0) *(float4*)(Cout + orow * ldc + n0 + tx4)      = hi0;
            if (cok1) *(float4*)(Cout + orow * ldc + n0 + tx4 + 64) = hi1;
        }
    }
}

// ---------------------------------------------------------------------------
// tf32 word projection v3 + __launch_bounds__(256, 2): 2 CTAs/SM.
// ---------------------------------------------------------------------------
__global__ __launch_bounds__(256, 2) void word_mma(
    const float* __restrict__ A, const float* __restrict__ Bm,
    const float* __restrict__ bias, float* __restrict__ Cout,
    const int* __restrict__ outIdx, const int* __restrict__ MvP)
{
    constexpr int ST = 20;
    __shared__ __align__(16) unsigned As[2][128 * ST];
    __shared__ __align__(16) unsigned Bs[2][128 * ST];

    int m0 = blockIdx.x * 128, n0 = blockIdx.y * 128;
    int Mv = __ldg(MvP);
    if (m0 >= Mv) return;

    int tid = threadIdx.x, lane = tid & 31, w = tid >> 5;
    int wm = w & 3, wn = w >> 2;
    int lrow = tid >> 2, q = tid & 3;
    const float4 z4 = make_float4(0.f, 0.f, 0.f, 0.f);

    const float4* Ag0 = (const float4*)(A + (size_t)(m0 + lrow)      * D) + q;
    const float4* Ag1 = (const float4*)(A + (size_t)(m0 + lrow + 64) * D) + q;
    int br0 = n0 + lrow, br1 = n0 + lrow + 64;
    bool bok0 = br0 < V, bok1 = br1 < V;
    const float4* Bg0 = (const float4*)(Bm + (size_t)(bok0 ? br0 : 0) * D) + q;
    const float4* Bg1 = (const float4*)(Bm + (size_t)(bok1 ? br1 : 0) * D) + q;

    int s0 = lrow * ST + q * 4;
    int s1 = (lrow + 64) * ST + q * 4;

    float acc[2][8][4];
    #pragma unroll
    for (int i = 0; i < 2; i++)
        #pragma unroll
        for (int j = 0; j < 8; j++)
            #pragma unroll
            for (int r = 0; r < 4; r++) acc[i][j][r] = 0.f;

    float4 pa0 = __ldg(Ag0), pa1 = __ldg(Ag1);
    float4 pb0 = bok0 ? __ldg(Bg0) : z4;
    float4 pb1 = bok1 ? __ldg(Bg1) : z4;
    {
        uint4 u;
        u.x=tf32_of(pa0.x); u.y=tf32_of(pa0.y); u.z=tf32_of(pa0.z); u.w=tf32_of(pa0.w);
        *(uint4*)&As[0][s0] = u;
        u.x=tf32_of(pa1.x); u.y=tf32_of(pa1.y); u.z=tf32_of(pa1.z); u.w=tf32_of(pa1.w);
        *(uint4*)&As[0][s1] = u;
        u.x=tf32_of(pb0.x); u.y=tf32_of(pb0.y); u.z=tf32_of(pb0.z); u.w=tf32_of(pb0.w);
        *(uint4*)&Bs[0][s0] = u;
        u.x=tf32_of(pb1.x); u.y=tf32_of(pb1.y); u.z=tf32_of(pb1.z); u.w=tf32_of(pb1.w);
        *(uint4*)&Bs[0][s1] = u;
    }
    __syncthreads();

    int g = lane >> 2, t4 = lane & 3;
    const int KT = D / 16;
    for (int kt = 0; kt < KT; kt++) {
        int cur = kt & 1;
        if (kt + 1 < KT) {
            int ko = (kt + 1) * 4;
            pa0 = __ldg(Ag0 + ko); pa1 = __ldg(Ag1 + ko);
            pb0 = bok0 ? __ldg(Bg0 + ko) : z4;
            pb1 = bok1 ? __ldg(Bg1 + ko) : z4;
        }
        #pragma unroll
        for (int ks = 0; ks < 2; ks++) {
            int kb = ks * 8;
            unsigned af[2][4], bf[8][2];
            #pragma unroll
            for (int i = 0; i < 2; i++) {
                int base = (wm * 32 + i * 16 + g) * ST + kb + t4;
                af[i][0] = As[cur][base];
                af[i][1] = As[cur][base + 8 * ST];
                af[i][2] = As[cur][base + 4];
                af[i][3] = As[cur][base + 8 * ST + 4];
            }
            #pragma unroll
            for (int j = 0; j < 8; j++) {
                int base = (wn * 64 + j * 8 + g) * ST + kb + t4;
                bf[j][0] = Bs[cur][base];
                bf[j][1] = Bs[cur][base + 4];
            }
            #pragma unroll
            for (int i = 0; i < 2; i++)
                #pragma unroll
                for (int j = 0; j < 8; j++)
                    mma_tf32(acc[i][j], af[i], bf[j]);
        }
        if (kt + 1 < KT) {
            int nb = 1 - cur;
            uint4 u;
            u.x=tf32_of(pa0.x); u.y=tf32_of(pa0.y); u.z=tf32_of(pa0.z); u.w=tf32_of(pa0.w);
            *(uint4*)&As[nb][s0] = u;
            u.x=tf32_of(pa1.x); u.y=tf32_of(pa1.y); u.z=tf32_of(pa1.z); u.w=tf32_of(pa1.w);
            *(uint4*)&As[nb][s1] = u;
            u.x=tf32_of(pb0.x); u.y=tf32_of(pb0.y); u.z=tf32_of(pb0.z); u.w=tf32_of(pb0.w);
            *(uint4*)&Bs[nb][s0] = u;
            u.x=tf32_of(pb1.x); u.y=tf32_of(pb1.y); u.z=tf32_of(pb1.z); u.w=tf32_of(pb1.w);
            *(uint4*)&Bs[nb][s1] = u;
        }
        __syncthreads();
    }

    int r0 = lane >> 2, tg = lane & 3;
    #pragma unroll
    for (int i = 0; i < 2; i++) {
        #pragma unroll
        for (int h = 0; h < 2; h++) {
            int gr = m0 + wm * 32 + i * 16 + r0 + h * 8;
            if (gr < Mv) {
                size_t orow = (size_t)__ldg(&outIdx[gr]);
                float* outr = Cout + orow * V;
                #pragma unroll
                for (int j = 0; j < 8; j++) {
                    int gc = n0 + wn * 64 + j * 8 + tg * 2;
                    if (gc < V) {
                        float b0 = __ldg(&bias[gc]), b1 = __ldg(&bias[gc + 1]);
                        float2 v;
                        v.x = acc[i][j][h * 2 + 0] + b0;
                        v.y = acc[i][j][h * 2 + 1] + b1;
                        *(float2*)(outr + gc) = v;
                    }
                }
            }
        }
    }
}

// ---------------------------------------------------------------------------
__global__ void zerofill(float* __restrict__ out)
{
    int r = blockIdx.x, b = r / T, t = r - b * T;
    if (t < d_dlen[b]) return;
    float4* p = (float4*)(out + (size_t)r * V);
    float4 z = make_float4(0.f, 0.f, 0.f, 0.f);
    for (int i = threadIdx.x; i < V / 4; i += blockDim.x) p[i] = z;
}

// ---------------------------------------------------------------------------
// persistent LSTM — byte-identical to the round-12 PASSING (1538us) version.
// ---------------------------------------------------------------------------
__global__ __launch_bounds__(256) void lstm_persist(const float* __restrict__ w_hh)
{
    __shared__ float w_s[512][16];
    __shared__ __align__(16) float hs[16][132];
    __shared__ float c_s[512];
    __shared__ int s_start[NB];
    __shared__ int s_nt[T];

    int tid = threadIdx.x, d0 = blockIdx.x * 4;

    #pragma unroll
    for (int s = 0; s < 8; s++) {
        int lin = tid + s * 256;
        int i = lin >> 7, q = lin & 127;
        int gc = (i >> 2) * 512 + d0 + (i & 3);
        float4 v = __ldg((const float4*)(w_hh + (size_t)gc * 512 + q * 4));
        w_s[q*4+0][i]=v.x; w_s[q*4+1][i]=v.y; w_s[q*4+2][i]=v.z; w_s[q*4+3][i]=v.w;
    }
    if (tid < NB) s_start[tid] = d_start[tid];
    if (tid < T)  s_nt[tid] = d_nt[tid];
    for (int e = tid; e < 512; e += 256) c_s[e] = 0.f;
    __syncthreads();

    int rp = tid >> 2, c4 = tid & 3;
    int row0 = tid >> 2, q2 = tid & 3;
    int row1 = row0 + 64;

    for (int t = 0; t < T; t++) {
        int nt = s_nt[t];
        int nt8 = (nt + 7) & ~7;
        bool cok = (2 * rp) < nt8;
        bool l0 = row0 < nt8, l1 = row1 < nt8;
        const float* hc = (t & 1) ? d_hB : d_hA;
        float*       hw = (t & 1) ? d_hA : d_hB;

        unsigned long long acc[4] = {0ull, 0ull, 0ull, 0ull};

        float4 v0, v1;
        if (l0) v0 = __ldcg((const float4*)(hc + (size_t)row0 * 512 + q2 * 4));
        if (l1) v1 = __ldcg((const float4*)(hc + (size_t)row1 * 512 + q2 * 4));

        for (int kc = 0; kc < 32; kc++) {
            if (l0) { hs[q2*4+0][row0]=v0.x; hs[q2*4+1][row0]=v0.y; hs[q2*4+2][row0]=v0.z; hs[q2*4+3][row0]=v0.w; }
            if (l1) { hs[q2*4+0][row1]=v1.x; hs[q2*4+1][row1]=v1.y; hs[q2*4+2][row1]=v1.z; hs[q2*4+3][row1]=v1.w; }
            __syncthreads();
            if (kc + 1 < 32) {
                int ko = (kc + 1) * 16 + q2 * 4;
                if (l0) v0 = __ldcg((const float4*)(hc + (size_t)row0 * 512 + ko));
                if (l1) v1 = __ldcg((const float4*)(hc + (size_t)row1 * 512 + ko));
            }
            if (cok) {
                #pragma unroll
                for (int k = 0; k < 16; k++) {
                    unsigned long long hp = *(const unsigned long long*)&hs[k][rp * 2];
                    float4 wv = *(const float4*)&w_s[kc * 16 + k][c4 * 4];
                    fma2(acc[0], hp, dup2(wv.x));
                    fma2(acc[1], hp, dup2(wv.y));
                    fma2(acc[2], hp, dup2(wv.z));
                    fma2(acc[3], hp, dup2(wv.w));
                }
            }
            __syncthreads();
        }
        #pragma unroll
        for (int j = 0; j < 4; j++) {
            float2 f = unpk(acc[j]);
            hs[c4 * 4 + j][rp * 2 + 0] = f.x;
            hs[c4 * 4 + j][rp * 2 + 1] = f.y;
        }
        __syncthreads();
        for (int e = tid; e < 512; e += 256) {
            int b = e >> 2, dd = e & 3;
            if (b < nt) {
                size_t cidx = (size_t)(s_start[b] + t);
                const float* xp = d_xproj + cidx * G + d0 + dd;
                float g0 = hs[dd][b]      + __ldg(xp);
                float g1 = hs[4 + dd][b]  + __ldg(xp + 512);
                float g2 = hs[8 + dd][b]  + __ldg(xp + 1024);
                float g3 = hs[12 + dd][b] + __ldg(xp + 1536);
                float gi = 1.f / (1.f + __expf(-g0));
                float gf = 1.f / (1.f + __expf(-g1));
                float gg = tanhf(g2);
                float go = 1.f / (1.f + __expf(-g3));
                float c  = c_s[e];
                float cn = gf * c + gi * gg;
                float hn = go * tanhf(cn);
                c_s[e] = cn;
                __stcg(hw + (size_t)b * 512 + d0 + dd, hn);
                d_Hbuf[cidx * 512 + d0 + dd] = hn;
            }
        }
        if (t < T - 1) {
            int tg2 = t + 1;
            __syncthreads();
            if (tid == 0) { __threadfence(); d_flags2[blockIdx.x] = tg2; }
            if (blockIdx.x == 0) {
                if (tid < NB) { while (d_flags2[tid] < tg2) __nanosleep(32); }
                __syncthreads();
                if (tid == 0) { __threadfence(); d_gen2 = tg2; }
            }
            if (tid == 0) { while (d_gen2 < tg2) __nanosleep(32); __threadfence(); }
            __syncthreads();
        }
    }
}

// ---------------------------------------------------------------------------
extern "C" void kernel_launch(void* const* d_in, const int* in_sizes, int n_in,
                              void* d_out, int out_size)
{
    const float* feats  = (const float*)d_in[0];
    const int*   caps   = (const int*)  d_in[1];
    const int*   clen   = (const int*)  d_in[2];
    const float* emb    = (const float*)d_in[3];
    const float* att1_w = (const float*)d_in[4];
    const float* att1_b = (const float*)d_in[5];
    const float* w_ih   = (const float*)d_in[6];
    const float* w_hh   = (const float*)d_in[7];
    const float* b_ih   = (const float*)d_in[8];
    const float* b_hh   = (const float*)d_in[9];
    const float* word_w = (const float*)d_in[10];
    const float* word_b = (const float*)d_in[11];
    float* out = (float*)d_out;

    float *xproj, *Hbuf, *bias2;
    int *tok, *vrow, *Sp;
    cudaGetSymbolAddress((void**)&xproj, d_xproj);
    cudaGetSymbolAddress((void**)&Hbuf,  d_Hbuf);
    cudaGetSymbolAddress((void**)&bias2, d_bias2);
    cudaGetSymbolAddress((void**)&tok,   d_tok);
    cudaGetSymbolAddress((void**)&vrow,  d_vrow);
    cudaGetSymbolAddress((void**)&Sp,    d_S);

    const long long PRED = (long long)NB * T * V;
    int write_tail = ((long long)out_size >= PRED + NB * L + 2 * NB) ? 1 : 0;

    prep_kernel<<<1, NB>>>(clen, caps, b_ih, b_hh, out, write_tail);
    mean_kernel<<<NB, 256>>>(feats);
    h0_kernel<<<dim3(NB, 4), 256>>>(att1_w, att1_b);

    gemm128<true, false><<<dim3(R / 128, G / 128), 256>>>(
        emb, E, tok, w_ih, bias2, xproj, G, nullptr, Sp, G, E);

    zerofill<<<R, 256>>>(out);

    lstm_persist<<<NB, 256>>>(w_hh);

    word_mma<<<dim3((R + 127) / 128, (V + 127) / 128), 256>>>(
        Hbuf, word_w, word_b, out, vrow, Sp);
}